// round 3
// baseline (speedup 1.0000x reference)
#include <cuda_runtime.h>
#include <math.h>

// Scratch: t[b,s] (B=128, S=4096) and per-block partial stats
__device__ float   g_t[128 * 4096];
__device__ double2 g_part[4096];          // >= B * CHUNKS

// ---------------------------------------------------------------------------
// Kernel 1: t[b,s] = w2·relu(w1·x + b1) + b2
// Quad-per-row mapping: lane L handles row R+(L>>2), column slice q=(L&3).
// 8 rows / warp-iteration, 8 front-batched LDG.128 per lane, reduction is a
// 2-level quad butterfly (4 SHFL) instead of a 5-level warp tree.
// ---------------------------------------------------------------------------
__global__ __launch_bounds__(256, 2)
void k_transform(const float* __restrict__ x,
                 const float* __restrict__ w1,
                 const float* __restrict__ b1,
                 const float* __restrict__ w2,
                 const float* __restrict__ b2,
                 int rows)
{
    const int lane = threadIdx.x & 31;
    const int q    = lane & 3;           // column slice within quad
    const int sub  = lane >> 2;          // row within octet (0..7)
    const int gwarp  = blockIdx.x * (blockDim.x >> 5) + (threadIdx.x >> 5);
    const int nwarps = gridDim.x * (blockDim.x >> 5);

    const float4* __restrict__ X = reinterpret_cast<const float4*>(x);
    const float4* __restrict__ W = reinterpret_cast<const float4*>(w1);

    // Per-lane weight slices: float4 indices q, q+4, ..., q+28 of each w1 row.
    float4 wa0[8], wa1[8];
    #pragma unroll
    for (int k = 0; k < 8; ++k) { wa0[k] = W[q + 4*k]; wa1[k] = W[32 + q + 4*k]; }
    const float bb0 = b1[0], bb1 = b1[1];
    const float c0 = w2[0], c1 = w2[1], cb = b2[0];

    const int octets = rows >> 3;
    for (int o = gwarp; o < octets; o += nwarps) {
        const int row = (o << 3) + sub;
        const size_t base = (size_t)row * 32 + q;

        float4 v[8];
        #pragma unroll
        for (int k = 0; k < 8; ++k) v[k] = X[base + 4*k];

        float d0 = 0.f, d1 = 0.f;
        #pragma unroll
        for (int k = 0; k < 8; ++k) {
            d0 += v[k].x*wa0[k].x + v[k].y*wa0[k].y + v[k].z*wa0[k].z + v[k].w*wa0[k].w;
            d1 += v[k].x*wa1[k].x + v[k].y*wa1[k].y + v[k].z*wa1[k].z + v[k].w*wa1[k].w;
        }
        // quad butterfly: all 4 lanes of the quad end with the full sums
        d0 += __shfl_xor_sync(0xffffffffu, d0, 1);
        d0 += __shfl_xor_sync(0xffffffffu, d0, 2);
        d1 += __shfl_xor_sync(0xffffffffu, d1, 1);
        d1 += __shfl_xor_sync(0xffffffffu, d1, 2);

        if (q == 0) {
            float h0 = fmaxf(d0 + bb0, 0.0f);
            float h1 = fmaxf(d1 + bb1, 0.0f);
            g_t[row] = fmaf(c1, h1, fmaf(c0, h0, cb));   // 8 lanes -> 32B STG
        }
    }
}

// ---------------------------------------------------------------------------
// Kernel 2a: per-chunk partial sums of log|t[i+2]-t[i]|.
// grid = B * CHUNKS blocks, 256 threads, 1 element per thread. No atomics.
// ---------------------------------------------------------------------------
__global__ __launch_bounds__(256)
void k_partial(int S, int C)
{
    const int b = blockIdx.x / C;
    const int c = blockIdx.x % C;
    const int tid = threadIdx.x;
    const int i = c * blockDim.x + tid;

    double s = 0.0, ss = 0.0;
    if (i < S - 2) {
        const float* __restrict__ tb = g_t + (size_t)b * S;
        float d = fabsf(tb[i + 2] - tb[i]);
        float l = logf(d + 1e-6f);
        s = (double)l; ss = (double)l * (double)l;
    }

    #pragma unroll
    for (int off = 16; off; off >>= 1) {
        s  += __shfl_xor_sync(0xffffffffu, s,  off);
        ss += __shfl_xor_sync(0xffffffffu, ss, off);
    }
    __shared__ double sh_s[8], sh_ss[8];
    const int wid = tid >> 5, lane = tid & 31;
    if (lane == 0) { sh_s[wid] = s; sh_ss[wid] = ss; }
    __syncthreads();
    if (wid == 0) {
        double ts  = (lane < 8) ? sh_s[lane]  : 0.0;
        double tss = (lane < 8) ? sh_ss[lane] : 0.0;
        #pragma unroll
        for (int off = 4; off; off >>= 1) {
            ts  += __shfl_xor_sync(0xffffffffu, ts,  off);
            tss += __shfl_xor_sync(0xffffffffu, tss, off);
        }
        if (lane == 0) g_part[blockIdx.x] = make_double2(ts, tss);
    }
}

// ---------------------------------------------------------------------------
// Kernel 2b: finalize stats, tanh head, broadcast-write output (float4).
// ---------------------------------------------------------------------------
__global__ __launch_bounds__(256)
void k_final(const float* __restrict__ w3,
             const float* __restrict__ b3,
             float* __restrict__ out,
             int S, int C, int dout)
{
    const int b = blockIdx.x;
    const int tid = threadIdx.x;
    __shared__ alignas(16) float sh_stats[2];
    __shared__ alignas(16) float sh_o[64];   // 16B-aligned: read back as float4

    if (tid < 32) {
        double s = 0.0, ss = 0.0;
        if (tid < C) { double2 p = g_part[b * C + tid]; s = p.x; ss = p.y; }
        #pragma unroll
        for (int off = 16; off; off >>= 1) {
            s  += __shfl_xor_sync(0xffffffffu, s,  off);
            ss += __shfl_xor_sync(0xffffffffu, ss, off);
        }
        if (tid == 0) {
            const double N = (double)(S - 2);
            double mean = s / N;
            double var  = (ss - s * s / N) / (N - 1.0);
            if (var < 0.0) var = 0.0;
            sh_stats[0] = (float)mean;
            sh_stats[1] = (float)sqrt(var);
        }
    }
    __syncthreads();

    if (tid < dout)
        sh_o[tid] = tanhf(sh_stats[0] * w3[2*tid] + sh_stats[1] * w3[2*tid + 1] + b3[tid]);
    __syncthreads();

    // out[b] is dout x dout identical rows; write as float4.
    float4* __restrict__ ob = reinterpret_cast<float4*>(out + (size_t)b * dout * dout);
    const float4* __restrict__ so = reinterpret_cast<const float4*>(sh_o);
    const int total4 = (dout * dout) >> 2;     // 1024
    const int row4   = dout >> 2;              // 16
    for (int k = tid; k < total4; k += blockDim.x)
        ob[k] = so[k & (row4 - 1)];
}

extern "C" void kernel_launch(void* const* d_in, const int* in_sizes, int n_in,
                              void* d_out, int out_size)
{
    const float* x  = (const float*)d_in[0];
    const float* w1 = (const float*)d_in[1];
    const float* b1 = (const float*)d_in[2];
    const float* w2 = (const float*)d_in[3];
    const float* b2 = (const float*)d_in[4];
    const float* w3 = (const float*)d_in[5];
    const float* b3 = (const float*)d_in[6];
    float* out = (float*)d_out;

    const int DOUT = 64;
    const int B    = out_size / (DOUT * DOUT);   // 128
    const int rows = in_sizes[0] / 128;          // B * S
    const int S    = rows / B;                   // 4096
    const int C    = (S + 255) / 256;            // 16 chunks per batch

    k_transform<<<296, 256>>>(x, w1, b1, w2, b2, rows);   // 2 CTA/SM, grid-stride
    k_partial<<<B * C, 256>>>(S, C);
    k_final<<<B, 256>>>(w3, b3, out, S, C, DOUT);
}